// round 15
// baseline (speedup 1.0000x reference)
#include <cuda_runtime.h>
#include <cuda_fp16.h>
#include <stdint.h>

// RGCN layer: out = relu( scatter_add_dst( x[src] @ W_rel[edge_type] ) + x @ W_self + bias )
// R15: occupancy push per R14 profile (occ 24%, regs 128, tensor 42% = latency-bound).
//      __launch_bounds__(256,3) (85-reg cap, 3 CTA/SM = 24 warps), 2-stage ring with
//      single barrier per chunk (fill c+1 after sync(c)). GEMM otherwise identical.

#define D    256
#define TM   128
#define TN   128
#define KC   64
#define NCH  4            // D / KC
#define RMAX 32
#define MAXSEG 1200000
#define MAXN 51200

__device__ int g_cnt[RMAX + 1];   // static-zeroed; re-zeroed by k_relu each run
__device__ int g_cur[RMAX + 1];
__device__ int g_off[RMAX + 2];
__device__ int g_srcbuf[MAXSEG];
__device__ int g_dstbuf[MAXSEG];
__device__ int g_ntiles;

__device__ __half g_xh[MAXN * D];
// W in fp16, layout [r][k][n] (input layout); self-loop appended as relation R
__device__ __half g_wh[(RMAX + 1) * D * D];

// block-local int64-vs-int32 probe over the first 256 index pairs
__device__ __forceinline__ int detect_is64(const int2* ei_pairs) {
    __shared__ int zcnt;
    if (threadIdx.x == 0) zcnt = 0;
    __syncthreads();
    if (threadIdx.x < 256 && ei_pairs[threadIdx.x].y == 0) atomicAdd(&zcnt, 1);
    __syncthreads();
    return zcnt > 128;
}

// ---------------------------------------------------------------------------
// launch #1: fused relation histogram + fp16 prep + bias init
__global__ void k_hist_prep(const void* __restrict__ et,
                            const int2* __restrict__ ei_pairs,
                            const float* __restrict__ x,
                            const float* __restrict__ W_rel,
                            const float* __restrict__ W_self,
                            const float* __restrict__ bias,
                            float* __restrict__ out,
                            int E, int total4, int wtotal4, int R) {
    int is64 = detect_is64(ei_pairs);
    __shared__ int h[RMAX + 1];
    if (threadIdx.x <= R) h[threadIdx.x] = 0;
    __syncthreads();

    int i = blockIdx.x * blockDim.x + threadIdx.x;
    if (i < E) {
        int r = is64 ? (int)((const long long*)et)[i] : ((const int*)et)[i];
        if (r < 0) r = 0;
        if (r >= R) r = R - 1;
        atomicAdd(&h[r], 1);
    }
    if (i < total4) {
        float4 v = ((const float4*)x)[i];
        __half2* dst = (__half2*)&g_xh[i * 4];
        dst[0] = __floats2half2_rn(v.x, v.y);
        dst[1] = __floats2half2_rn(v.z, v.w);
        ((float4*)out)[i] = ((const float4*)bias)[i & (D / 4 - 1)];
    }
    if (i < wtotal4) {
        int wr = R * D * D / 4;
        float4 v = (i < wr) ? ((const float4*)W_rel)[i]
                            : ((const float4*)W_self)[i - wr];
        __half2* dst = (__half2*)&g_wh[i * 4];
        dst[0] = __floats2half2_rn(v.x, v.y);
        dst[1] = __floats2half2_rn(v.z, v.w);
    }
    __syncthreads();
    if (threadIdx.x <= R && h[threadIdx.x]) atomicAdd(&g_cnt[threadIdx.x], h[threadIdx.x]);
}

// launch #2
__global__ void k_scan(int R, int N) {
    g_cnt[R] = N;
    int off = 0;
    for (int r = 0; r <= R; r++) {
        g_off[r] = off;
        g_cur[r] = off;
        off += ((g_cnt[r] + TM - 1) / TM) * TM;
    }
    g_off[R + 1] = off;
    g_ntiles = off / TM;
}

// launch #3: two-phase scatter + self-loops + padding (disjoint index ranges)
__global__ void k_scatter(const void* __restrict__ ei,
                          const void* __restrict__ et,
                          int E, int N, int R) {
    int is64 = detect_is64((const int2*)ei);
    __shared__ int cnt[RMAX + 1];
    __shared__ int base[RMAX + 1];
    int i = blockIdx.x * blockDim.x + threadIdx.x;

    if (threadIdx.x <= R) cnt[threadIdx.x] = 0;
    __syncthreads();

    int r = -1, s = 0, d = 0, slot = 0;
    if (i < E) {
        if (is64) {
            r = (int)((const long long*)et)[i];
            s = (int)((const long long*)ei)[i];
            d = (int)((const long long*)ei)[E + i];
        } else {
            r = ((const int*)et)[i];
            s = ((const int*)ei)[i];
            d = ((const int*)ei)[E + i];
        }
        if (r < 0) r = 0;
        if (r >= R) r = R - 1;
        if (s < 0 || s >= N) s = 0;
        if (d < 0 || d >= N) d = 0;
        slot = atomicAdd(&cnt[r], 1);
    }
    __syncthreads();
    if (threadIdx.x <= R && cnt[threadIdx.x] > 0)
        base[threadIdx.x] = atomicAdd(&g_cur[threadIdx.x], cnt[threadIdx.x]);
    __syncthreads();

    if (r >= 0) {
        int p = base[r] + slot;
        g_srcbuf[p] = s;
        g_dstbuf[p] = d;
    } else if (i >= E && i < E + N) {
        int n = i - E;
        int p = g_off[R] + n;
        g_srcbuf[p] = n;
        g_dstbuf[p] = n;
    } else if (i >= E + N) {
        int j = i - (E + N);
        int rr = j / TM;
        int jj = j % TM;
        if (rr <= R) {
            int idx = g_off[rr] + g_cnt[rr] + jj;
            if (idx < g_off[rr + 1]) {
                g_srcbuf[idx] = -1;
                g_dstbuf[idx] = 0;
            }
        }
    }
}

// launch #5 (vectorized relu + counter reset for next invocation)
__global__ void k_relu(float* __restrict__ out, int total4, int R) {
    int i = blockIdx.x * blockDim.x + threadIdx.x;
    if (i < total4) {
        float4 v = ((const float4*)out)[i];
        v.x = fmaxf(v.x, 0.0f);
        v.y = fmaxf(v.y, 0.0f);
        v.z = fmaxf(v.z, 0.0f);
        v.w = fmaxf(v.w, 0.0f);
        ((float4*)out)[i] = v;
    }
    if (blockIdx.x == 0 && threadIdx.x <= R) g_cnt[threadIdx.x] = 0;
}

// ---------------------------------------------------------------------------
__device__ __forceinline__ uint32_t smem_u32(const void* p) {
    return (uint32_t)__cvta_generic_to_shared(p);
}

__device__ __forceinline__ void cpa16(uint32_t dst, const void* src, int sz) {
    asm volatile("cp.async.cg.shared.global [%0], [%1], 16, %2;"
                 :: "r"(dst), "l"(src), "r"(sz) : "memory");
}

__device__ __forceinline__ void ldsm_x4(uint32_t* r, uint32_t addr) {
    asm volatile("ldmatrix.sync.aligned.m8n8.x4.shared.b16 {%0,%1,%2,%3}, [%4];"
                 : "=r"(r[0]), "=r"(r[1]), "=r"(r[2]), "=r"(r[3]) : "r"(addr));
}

__device__ __forceinline__ void ldsm_x4_t(uint32_t* r, uint32_t addr) {
    asm volatile("ldmatrix.sync.aligned.m8n8.x4.trans.shared.b16 {%0,%1,%2,%3}, [%4];"
                 : "=r"(r[0]), "=r"(r[1]), "=r"(r[2]), "=r"(r[3]) : "r"(addr));
}

__device__ __forceinline__ void mma_f16(float* c, const uint32_t* a, const uint32_t* b) {
    asm volatile(
        "mma.sync.aligned.m16n8k16.row.col.f32.f16.f16.f32 "
        "{%0,%1,%2,%3}, {%4,%5,%6,%7}, {%8,%9}, {%0,%1,%2,%3};"
        : "+f"(c[0]), "+f"(c[1]), "+f"(c[2]), "+f"(c[3])
        : "r"(a[0]), "r"(a[1]), "r"(a[2]), "r"(a[3]), "r"(b[0]), "r"(b[1]));
}

// smem per stage: A 128 rows x 144B (64 fp16 + 8 pad) = 18432; B 64 rows x 272B = 17408
#define ASTRB 144
#define BSTRB 272
#define OFF_A  0
#define OFF_B  18432
#define SSTAGE 35840
#define NSTG   2
#define OFF_SRC (NSTG * SSTAGE)          // 71680
#define OFF_DST (OFF_SRC + 512)
#define SMEM_TOTAL (OFF_DST + 512)       // 72704  (3 CTAs: 218112 <= 233472)

// launch #4 — grid: (tiles_max, 2); block 256 = 8 warps; warp grid 4(M) x 2(N)
__global__ __launch_bounds__(256, 3) void k_gemm(float* __restrict__ out, int R) {
    extern __shared__ __align__(16) char sh[];
    int t = blockIdx.x;
    if (t >= g_ntiles) return;
    int row0 = t * TM;

    int rel = 0;
    while (g_off[rel + 1] <= row0) rel++;
    int relk = rel * D;                       // W row base in [r*D + k][n]

    int n0 = blockIdx.y * TN;
    int tid = threadIdx.x;
    int warp = tid >> 5;
    int lane = tid & 31;
    int wm = (warp & 3) * 32;      // M offset (4 warps along M)
    int wn = (warp >> 2) * 64;     // N offset (2 warps along N)

    int* s_src = (int*)(sh + OFF_SRC);
    int* s_dst = (int*)(sh + OFF_DST);
    if (tid < TM) {
        s_src[tid] = g_srcbuf[row0 + tid];
        s_dst[tid] = g_dstbuf[row0 + tid];
    }
    __syncthreads();

    uint32_t shb = smem_u32(sh);

    // per chunk: A ops j (0..1023): row = j>>3, seg = j&7 (16B each)
    //            B ops j (0..1023): row = j>>4, seg = j&15
    #define FILL(stg, c) do {                                                  \
        uint32_t sb = shb + (stg) * SSTAGE;                                    \
        int k0_ = (c) * KC;                                                    \
        _Pragma("unroll")                                                      \
        for (int ii = 0; ii < 4; ii++) {                                       \
            int j = tid + ii * 256;                                            \
            int rr = j >> 3, sg = j & 7;                                       \
            int sr = s_src[rr];                                                \
            int sz = (sr < 0) ? 0 : 16;                                        \
            size_t gi = (size_t)max(sr, 0) * D + k0_ + sg * 8;                 \
            cpa16(sb + OFF_A + rr * ASTRB + sg * 16, &g_xh[gi], sz);           \
            int br = j >> 4, bs = j & 15;                                      \
            size_t bi = (size_t)(relk + k0_ + br) * D + n0 + bs * 8;           \
            cpa16(sb + OFF_B + br * BSTRB + bs * 16, &g_wh[bi], 16);           \
        }                                                                      \
        asm volatile("cp.async.commit_group;" ::: "memory");                   \
    } while (0)

    float acc[2][8][4];
    #pragma unroll
    for (int mi = 0; mi < 2; mi++)
        #pragma unroll
        for (int g = 0; g < 8; g++)
            #pragma unroll
            for (int j = 0; j < 4; j++) acc[mi][g][j] = 0.0f;

    // ldmatrix lane addressing
    int a_row = (lane & 15);                  // + wm + mi*16
    int a_cbyte = (lane >> 4) << 4;           // 0 / 16 bytes
    int b_mat = lane >> 3;
    int b_rowoff = (lane & 7) + (b_mat & 1) * 8;
    int b_cbyte = ((b_mat >> 1) << 3) * 2;    // 0 / 16 bytes within 16-col pair

    FILL(0, 0);

    #pragma unroll 1
    for (int c = 0; c < NCH; c++) {
        asm volatile("cp.async.wait_group 0;" ::: "memory");
        __syncthreads();
        // fill chunk c+1 into stage (c+1)&1: its last readers (chunk c-1)
        // finished compute before this barrier — safe with 2 stages.
        if (c + 1 < NCH) FILL((c + 1) & 1, c + 1);

        uint32_t sb = shb + (c & 1) * SSTAGE;
        #pragma unroll
        for (int ks = 0; ks < 4; ks++) {       // four k16 steps per chunk
            uint32_t a[2][4];
            #pragma unroll
            for (int mi = 0; mi < 2; mi++)
                ldsm_x4(a[mi], sb + OFF_A + (wm + mi * 16 + a_row) * ASTRB
                               + ks * 32 + a_cbyte);

            #pragma unroll
            for (int p = 0; p < 4; p++) {      // 16-col pairs within 64
                uint32_t b[4];
                ldsm_x4_t(b, sb + OFF_B + (ks * 16 + b_rowoff) * BSTRB
                             + wn * 2 + p * 32 + b_cbyte);
                #pragma unroll
                for (int mi = 0; mi < 2; mi++) {
                    mma_f16(acc[mi][2 * p],     a[mi], &b[0]);
                    mma_f16(acc[mi][2 * p + 1], a[mi], &b[2]);
                }
            }
        }
    }

    // ---- epilogue: red.global.add.v2 straight from registers
    #pragma unroll
    for (int mi = 0; mi < 2; mi++) {
        int lr0 = wm + mi * 16 + (lane >> 2);
        int lr1 = lr0 + 8;
        int s0 = s_src[lr0], s1 = s_src[lr1];
        long long d0 = (long long)s_dst[lr0] * D;
        long long d1 = (long long)s_dst[lr1] * D;
        int colb = n0 + wn + ((lane & 3) << 1);
        #pragma unroll
        for (int g = 0; g < 8; g++) {
            int col = colb + g * 8;
            if (s0 >= 0) {
                float* p = out + d0 + col;
                asm volatile("red.global.add.v2.f32 [%0], {%1, %2};"
                             :: "l"(p), "f"(acc[mi][g][0]), "f"(acc[mi][g][1]) : "memory");
            }
            if (s1 >= 0) {
                float* p = out + d1 + col;
                asm volatile("red.global.add.v2.f32 [%0], {%1, %2};"
                             :: "l"(p), "f"(acc[mi][g][2]), "f"(acc[mi][g][3]) : "memory");
            }
        }
    }
}

// ---------------------------------------------------------------------------
extern "C" void kernel_launch(void* const* d_in, const int* in_sizes, int n_in,
                              void* d_out, int out_size) {
    // Bind inputs by element count (all six pairwise distinct):
    //   bias(256) < W_self(65,536) < edge_type(800k) < W_rel(1,048,576)
    //   < edge_index(1.6M) < x(12.8M)
    int order[16];
    for (int i = 0; i < n_in; i++) order[i] = i;
    for (int a = 0; a < n_in; a++)
        for (int b = a + 1; b < n_in; b++)
            if (in_sizes[order[b]] < in_sizes[order[a]]) {
                int t = order[a]; order[a] = order[b]; order[b] = t;
            }
    const float* bias   = (const float*)d_in[order[0]];
    const float* W_self = (const float*)d_in[order[1]];
    const void*  et     = d_in[order[2]];
    const float* W_rel  = (const float*)d_in[order[3]];
    const void*  ei     = d_in[order[4]];
    const float* x      = (const float*)d_in[order[5]];

    int E = in_sizes[order[2]];
    int N = in_sizes[order[5]] / D;
    int R = in_sizes[order[3]] / (D * D);
    if (R < 1) R = 1;
    if (R > RMAX - 1) R = RMAX - 1;
    if (N > MAXN) N = MAXN;

    float* out = (float*)d_out;
    int total = N * D;
    int wtotal = (R + 1) * D * D;

    // my launches: 1 hist+prep, 2 scan, 3 scatter, 4 GEMM (profiled slot), 5 relu
    int hp_total = total / 4;
    if (hp_total < E) hp_total = E;
    k_hist_prep<<<(hp_total + 255) / 256, 256>>>(et, (const int2*)ei, x, W_rel,
                                                 W_self, bias, out,
                                                 E, total / 4, wtotal / 4, R);
    k_scan<<<1, 1>>>(R, N);
    int scat_total = E + N + (R + 1) * TM;
    k_scatter<<<(scat_total + 255) / 256, 256>>>(ei, et, E, N, R);

    cudaFuncSetAttribute(k_gemm, cudaFuncAttributeMaxDynamicSharedMemorySize, SMEM_TOTAL);
    int tiles_max = (E + TM - 1) / TM + R + (N + TM - 1) / TM + 1;
    dim3 grid(tiles_max, D / TN);
    k_gemm<<<grid, 256, SMEM_TOTAL>>>(out, R);

    k_relu<<<(total / 4 + 255) / 256, 256>>>(out, total / 4, R);
}

// round 16
// speedup vs baseline: 1.6127x; 1.6127x over previous
#include <cuda_runtime.h>
#include <cuda_fp16.h>
#include <stdint.h>

// RGCN layer: out = relu( scatter_add_dst( x[src] @ W_rel[edge_type] ) + x @ W_self + bias )
// R16: exact revert to R13 (best measured: 494us). Single-term fp16 gather-GEMM,
//      mma.m16n8k16, TM=TN=128, KC=64, 3-stage cp.async ring, 4x2 warp grid
//      (128 regs, 2 CTA/SM, no spills), direct red.v2 epilogue, vectorized
//      prep/relu, two-phase scatter.

#define D    256
#define TM   128
#define TN   128
#define KC   64
#define NCH  4            // D / KC
#define RMAX 32
#define MAXSEG 1200000
#define MAXN 51200

__device__ int g_cnt[RMAX + 1];
__device__ int g_cur[RMAX + 1];
__device__ int g_off[RMAX + 2];
__device__ int g_srcbuf[MAXSEG];
__device__ int g_dstbuf[MAXSEG];
__device__ int g_ntiles;
__device__ int g_is64;

__device__ __half g_xh[MAXN * D];
// W in fp16, layout [r][k][n] (input layout); self-loop appended as relation R
__device__ __half g_wh[(RMAX + 1) * D * D];

// ---------------------------------------------------------------------------
// launch #1: dtype probe + counter zeroing
__global__ void k_detect(const int2* __restrict__ ei_pairs, int npairs, int R) {
    __shared__ int zcnt;
    if (threadIdx.x == 0) zcnt = 0;
    if (threadIdx.x <= R) g_cnt[threadIdx.x] = 0;
    __syncthreads();
    int i = threadIdx.x;
    if (i < npairs && ei_pairs[i].y == 0) atomicAdd(&zcnt, 1);
    __syncthreads();
    if (threadIdx.x == 0) g_is64 = (zcnt > npairs / 2) ? 1 : 0;
}

// launch #2
__global__ void k_hist(const void* __restrict__ et, int E, int R) {
    __shared__ int h[RMAX + 1];
    if (threadIdx.x <= R) h[threadIdx.x] = 0;
    __syncthreads();
    int i = blockIdx.x * blockDim.x + threadIdx.x;
    if (i < E) {
        int r = g_is64 ? (int)((const long long*)et)[i] : ((const int*)et)[i];
        if (r < 0) r = 0;
        if (r >= R) r = R - 1;
        atomicAdd(&h[r], 1);
    }
    __syncthreads();
    if (threadIdx.x <= R && h[threadIdx.x]) atomicAdd(&g_cnt[threadIdx.x], h[threadIdx.x]);
}

// launch #3
__global__ void k_scan(int R, int N) {
    g_cnt[R] = N;
    int off = 0;
    for (int r = 0; r <= R; r++) {
        g_off[r] = off;
        g_cur[r] = off;
        off += ((g_cnt[r] + TM - 1) / TM) * TM;
    }
    g_off[R + 1] = off;
    g_ntiles = off / TM;
}

// launch #4: two-phase scatter + self-loops + padding (disjoint index ranges)
__global__ void k_scatter(const void* __restrict__ ei,
                          const void* __restrict__ et,
                          int E, int N, int R) {
    __shared__ int cnt[RMAX + 1];
    __shared__ int base[RMAX + 1];
    int i = blockIdx.x * blockDim.x + threadIdx.x;
    int is64 = g_is64;

    if (threadIdx.x <= R) cnt[threadIdx.x] = 0;
    __syncthreads();

    int r = -1, s = 0, d = 0, slot = 0;
    if (i < E) {
        if (is64) {
            r = (int)((const long long*)et)[i];
            s = (int)((const long long*)ei)[i];
            d = (int)((const long long*)ei)[E + i];
        } else {
            r = ((const int*)et)[i];
            s = ((const int*)ei)[i];
            d = ((const int*)ei)[E + i];
        }
        if (r < 0) r = 0;
        if (r >= R) r = R - 1;
        if (s < 0 || s >= N) s = 0;
        if (d < 0 || d >= N) d = 0;
        slot = atomicAdd(&cnt[r], 1);
    }
    __syncthreads();
    if (threadIdx.x <= R && cnt[threadIdx.x] > 0)
        base[threadIdx.x] = atomicAdd(&g_cur[threadIdx.x], cnt[threadIdx.x]);
    __syncthreads();

    if (r >= 0) {
        int p = base[r] + slot;
        g_srcbuf[p] = s;
        g_dstbuf[p] = d;
    } else if (i >= E && i < E + N) {
        int n = i - E;
        int p = g_off[R] + n;
        g_srcbuf[p] = n;
        g_dstbuf[p] = n;
    } else if (i >= E + N) {
        int j = i - (E + N);
        int rr = j / TM;
        int jj = j % TM;
        if (rr <= R) {
            int idx = g_off[rr] + g_cnt[rr] + jj;
            if (idx < g_off[rr + 1]) {
                g_srcbuf[idx] = -1;
                g_dstbuf[idx] = 0;
            }
        }
    }
}

// launch #5: x, W -> fp16 (vectorized: 4 elems/thread); init out = bias
__global__ void k_prep(const float* __restrict__ x,
                       const float* __restrict__ W_rel,
                       const float* __restrict__ W_self,
                       const float* __restrict__ bias,
                       float* __restrict__ out,
                       int total4, int wtotal4, int R) {
    int i = blockIdx.x * blockDim.x + threadIdx.x;
    if (i < total4) {
        float4 v = ((const float4*)x)[i];
        __half2* dst = (__half2*)&g_xh[i * 4];
        dst[0] = __floats2half2_rn(v.x, v.y);
        dst[1] = __floats2half2_rn(v.z, v.w);
        ((float4*)out)[i] = ((const float4*)bias)[i & (D / 4 - 1)];
    }
    if (i < wtotal4) {
        int wr = R * D * D / 4;
        float4 v = (i < wr) ? ((const float4*)W_rel)[i]
                            : ((const float4*)W_self)[i - wr];
        __half2* dst = (__half2*)&g_wh[i * 4];
        dst[0] = __floats2half2_rn(v.x, v.y);
        dst[1] = __floats2half2_rn(v.z, v.w);
    }
}

// launch #7 (vectorized)
__global__ void k_relu(float* __restrict__ out, int total4) {
    int i = blockIdx.x * blockDim.x + threadIdx.x;
    if (i < total4) {
        float4 v = ((const float4*)out)[i];
        v.x = fmaxf(v.x, 0.0f);
        v.y = fmaxf(v.y, 0.0f);
        v.z = fmaxf(v.z, 0.0f);
        v.w = fmaxf(v.w, 0.0f);
        ((float4*)out)[i] = v;
    }
}

// ---------------------------------------------------------------------------
__device__ __forceinline__ uint32_t smem_u32(const void* p) {
    return (uint32_t)__cvta_generic_to_shared(p);
}

__device__ __forceinline__ void cpa16(uint32_t dst, const void* src, int sz) {
    asm volatile("cp.async.cg.shared.global [%0], [%1], 16, %2;"
                 :: "r"(dst), "l"(src), "r"(sz) : "memory");
}

__device__ __forceinline__ void ldsm_x4(uint32_t* r, uint32_t addr) {
    asm volatile("ldmatrix.sync.aligned.m8n8.x4.shared.b16 {%0,%1,%2,%3}, [%4];"
                 : "=r"(r[0]), "=r"(r[1]), "=r"(r[2]), "=r"(r[3]) : "r"(addr));
}

__device__ __forceinline__ void ldsm_x4_t(uint32_t* r, uint32_t addr) {
    asm volatile("ldmatrix.sync.aligned.m8n8.x4.trans.shared.b16 {%0,%1,%2,%3}, [%4];"
                 : "=r"(r[0]), "=r"(r[1]), "=r"(r[2]), "=r"(r[3]) : "r"(addr));
}

__device__ __forceinline__ void mma_f16(float* c, const uint32_t* a, const uint32_t* b) {
    asm volatile(
        "mma.sync.aligned.m16n8k16.row.col.f32.f16.f16.f32 "
        "{%0,%1,%2,%3}, {%4,%5,%6,%7}, {%8,%9}, {%0,%1,%2,%3};"
        : "+f"(c[0]), "+f"(c[1]), "+f"(c[2]), "+f"(c[3])
        : "r"(a[0]), "r"(a[1]), "r"(a[2]), "r"(a[3]), "r"(b[0]), "r"(b[1]));
}

// smem per stage: A 128 rows x 144B (64 fp16 + 8 pad) = 18432; B 64 rows x 272B = 17408
#define ASTRB 144
#define BSTRB 272
#define OFF_A  0
#define OFF_B  18432
#define SSTAGE 35840
#define NSTG   3
#define OFF_SRC (NSTG * SSTAGE)          // 107520
#define OFF_DST (OFF_SRC + 512)
#define SMEM_TOTAL (OFF_DST + 512)       // 108544

// grid: (tiles_max, 2); block 256 = 8 warps; warp grid 4(M) x 2(N), tile 32x64
__global__ __launch_bounds__(256, 2) void k_gemm(float* __restrict__ out, int R) {
    extern __shared__ __align__(16) char sh[];
    int t = blockIdx.x;
    if (t >= g_ntiles) return;
    int row0 = t * TM;

    int rel = 0;
    while (g_off[rel + 1] <= row0) rel++;
    int relk = rel * D;                       // W row base in [r*D + k][n]

    int n0 = blockIdx.y * TN;
    int tid = threadIdx.x;
    int warp = tid >> 5;
    int lane = tid & 31;
    int wm = (warp & 3) * 32;      // M offset (4 warps along M)
    int wn = (warp >> 2) * 64;     // N offset (2 warps along N)

    int* s_src = (int*)(sh + OFF_SRC);
    int* s_dst = (int*)(sh + OFF_DST);
    if (tid < TM) {
        s_src[tid] = g_srcbuf[row0 + tid];
        s_dst[tid] = g_dstbuf[row0 + tid];
    }
    __syncthreads();

    uint32_t shb = smem_u32(sh);

    // per chunk: A ops j (0..1023): row = j>>3, seg = j&7 (16B each)
    //            B ops j (0..1023): row = j>>4, seg = j&15
    #define FILL(stg, c) do {                                                  \
        uint32_t sb = shb + (stg) * SSTAGE;                                    \
        int k0_ = (c) * KC;                                                    \
        _Pragma("unroll")                                                      \
        for (int ii = 0; ii < 4; ii++) {                                       \
            int j = tid + ii * 256;                                            \
            int rr = j >> 3, sg = j & 7;                                       \
            int sr = s_src[rr];                                                \
            int sz = (sr < 0) ? 0 : 16;                                        \
            size_t gi = (size_t)max(sr, 0) * D + k0_ + sg * 8;                 \
            cpa16(sb + OFF_A + rr * ASTRB + sg * 16, &g_xh[gi], sz);           \
            int br = j >> 4, bs = j & 15;                                      \
            size_t bi = (size_t)(relk + k0_ + br) * D + n0 + bs * 8;           \
            cpa16(sb + OFF_B + br * BSTRB + bs * 16, &g_wh[bi], 16);           \
        }                                                                      \
        asm volatile("cp.async.commit_group;" ::: "memory");                   \
    } while (0)

    float acc[2][8][4];
    #pragma unroll
    for (int mi = 0; mi < 2; mi++)
        #pragma unroll
        for (int g = 0; g < 8; g++)
            #pragma unroll
            for (int j = 0; j < 4; j++) acc[mi][g][j] = 0.0f;

    // ldmatrix lane addressing
    int a_row = (lane & 15);                  // + wm + mi*16
    int a_cbyte = (lane >> 4) << 4;           // 0 / 16 bytes
    int b_mat = lane >> 3;
    int b_rowoff = (lane & 7) + (b_mat & 1) * 8;
    int b_cbyte = ((b_mat >> 1) << 3) * 2;    // 0 / 16 bytes within 16-col pair

    FILL(0, 0);
    FILL(1, 1);

    #pragma unroll 1
    for (int c = 0; c < NCH; c++) {
        if (c < NCH - 1)
            asm volatile("cp.async.wait_group 1;" ::: "memory");
        else
            asm volatile("cp.async.wait_group 0;" ::: "memory");
        __syncthreads();
        // fill chunk c+2 into the stage last read at chunk c-1 (safe post-sync)
        if (c + 2 < NCH) FILL((c + 2) % NSTG, c + 2);

        uint32_t sb = shb + (c % NSTG) * SSTAGE;
        #pragma unroll
        for (int ks = 0; ks < 4; ks++) {       // four k16 steps per chunk
            uint32_t a[2][4];
            #pragma unroll
            for (int mi = 0; mi < 2; mi++)
                ldsm_x4(a[mi], sb + OFF_A + (wm + mi * 16 + a_row) * ASTRB
                               + ks * 32 + a_cbyte);

            #pragma unroll
            for (int p = 0; p < 4; p++) {      // 16-col pairs within 64
                uint32_t b[4];
                ldsm_x4_t(b, sb + OFF_B + (ks * 16 + b_rowoff) * BSTRB
                             + wn * 2 + p * 32 + b_cbyte);
                #pragma unroll
                for (int mi = 0; mi < 2; mi++) {
                    mma_f16(acc[mi][2 * p],     a[mi], &b[0]);
                    mma_f16(acc[mi][2 * p + 1], a[mi], &b[2]);
                }
            }
        }
    }

    // ---- epilogue: red.global.add.v2 straight from registers (measured best)
    #pragma unroll
    for (int mi = 0; mi < 2; mi++) {
        int lr0 = wm + mi * 16 + (lane >> 2);
        int lr1 = lr0 + 8;
        int s0 = s_src[lr0], s1 = s_src[lr1];
        long long d0 = (long long)s_dst[lr0] * D;
        long long d1 = (long long)s_dst[lr1] * D;
        int colb = n0 + wn + ((lane & 3) << 1);
        #pragma unroll
        for (int g = 0; g < 8; g++) {
            int col = colb + g * 8;
            if (s0 >= 0) {
                float* p = out + d0 + col;
                asm volatile("red.global.add.v2.f32 [%0], {%1, %2};"
                             :: "l"(p), "f"(acc[mi][g][0]), "f"(acc[mi][g][1]) : "memory");
            }
            if (s1 >= 0) {
                float* p = out + d1 + col;
                asm volatile("red.global.add.v2.f32 [%0], {%1, %2};"
                             :: "l"(p), "f"(acc[mi][g][2]), "f"(acc[mi][g][3]) : "memory");
            }
        }
    }
}

// ---------------------------------------------------------------------------
extern "C" void kernel_launch(void* const* d_in, const int* in_sizes, int n_in,
                              void* d_out, int out_size) {
    // Bind inputs by element count (all six pairwise distinct):
    //   bias(256) < W_self(65,536) < edge_type(800k) < W_rel(1,048,576)
    //   < edge_index(1.6M) < x(12.8M)
    int order[16];
    for (int i = 0; i < n_in; i++) order[i] = i;
    for (int a = 0; a < n_in; a++)
        for (int b = a + 1; b < n_in; b++)
            if (in_sizes[order[b]] < in_sizes[order[a]]) {
                int t = order[a]; order[a] = order[b]; order[b] = t;
            }
    const float* bias   = (const float*)d_in[order[0]];
    const float* W_self = (const float*)d_in[order[1]];
    const void*  et     = d_in[order[2]];
    const float* W_rel  = (const float*)d_in[order[3]];
    const void*  ei     = d_in[order[4]];
    const float* x      = (const float*)d_in[order[5]];

    int E = in_sizes[order[2]];
    int N = in_sizes[order[5]] / D;
    int R = in_sizes[order[3]] / (D * D);
    if (R < 1) R = 1;
    if (R > RMAX - 1) R = RMAX - 1;
    if (N > MAXN) N = MAXN;

    float* out = (float*)d_out;
    int total = N * D;
    int wtotal = (R + 1) * D * D;

    k_detect<<<1, 256>>>((const int2*)ei, 256, R);
    k_hist<<<(E + 255) / 256, 256>>>(et, E, R);
    k_scan<<<1, 1>>>(R, N);
    int scat_total = E + N + (R + 1) * TM;
    k_scatter<<<(scat_total + 255) / 256, 256>>>(ei, et, E, N, R);
    k_prep<<<(total / 4 + 255) / 256, 256>>>(x, W_rel, W_self, bias, out,
                                             total / 4, wtotal / 4, R);

    cudaFuncSetAttribute(k_gemm, cudaFuncAttributeMaxDynamicSharedMemorySize, SMEM_TOTAL);
    int tiles_max = (E + TM - 1) / TM + R + (N + TM - 1) / TM + 1;
    dim3 grid(tiles_max, D / TN);
    k_gemm<<<grid, 256, SMEM_TOTAL>>>(out, R);

    k_relu<<<(total / 4 + 255) / 256, 256>>>(out, total / 4);
}

// round 17
// speedup vs baseline: 1.6236x; 1.0067x over previous
#include <cuda_runtime.h>
#include <cuda_fp16.h>
#include <stdint.h>

// RGCN layer: out = relu( scatter_add_dst( x[src] @ W_rel[edge_type] ) + x @ W_self + bias )
// R17: A-resident fused-y GEMM. One CTA per 128-edge tile holds the full A tile
//      (128x256 fp16, XOR-swizzled 512B rows) in smem and loops y in {0,1},
//      streaming B through a 2-stage cp.async ring. Halves CTA count, A-gather
//      traffic, and per-tile prologue. mma path / epilogue identical to R16.

#define D    256
#define TM   128
#define KC   64
#define NCH  4            // D / KC
#define RMAX 32
#define MAXSEG 1200000
#define MAXN 51200

__device__ int g_cnt[RMAX + 1];
__device__ int g_cur[RMAX + 1];
__device__ int g_off[RMAX + 2];
__device__ int g_srcbuf[MAXSEG];
__device__ int g_dstbuf[MAXSEG];
__device__ int g_ntiles;
__device__ int g_is64;

__device__ __half g_xh[MAXN * D];
// W in fp16, layout [r][k][n] (input layout); self-loop appended as relation R
__device__ __half g_wh[(RMAX + 1) * D * D];

// ---------------------------------------------------------------------------
// launch #1: dtype probe + counter zeroing
__global__ void k_detect(const int2* __restrict__ ei_pairs, int npairs, int R) {
    __shared__ int zcnt;
    if (threadIdx.x == 0) zcnt = 0;
    if (threadIdx.x <= R) g_cnt[threadIdx.x] = 0;
    __syncthreads();
    int i = threadIdx.x;
    if (i < npairs && ei_pairs[i].y == 0) atomicAdd(&zcnt, 1);
    __syncthreads();
    if (threadIdx.x == 0) g_is64 = (zcnt > npairs / 2) ? 1 : 0;
}

// launch #2
__global__ void k_hist(const void* __restrict__ et, int E, int R) {
    __shared__ int h[RMAX + 1];
    if (threadIdx.x <= R) h[threadIdx.x] = 0;
    __syncthreads();
    int i = blockIdx.x * blockDim.x + threadIdx.x;
    if (i < E) {
        int r = g_is64 ? (int)((const long long*)et)[i] : ((const int*)et)[i];
        if (r < 0) r = 0;
        if (r >= R) r = R - 1;
        atomicAdd(&h[r], 1);
    }
    __syncthreads();
    if (threadIdx.x <= R && h[threadIdx.x]) atomicAdd(&g_cnt[threadIdx.x], h[threadIdx.x]);
}

// launch #3
__global__ void k_scan(int R, int N) {
    g_cnt[R] = N;
    int off = 0;
    for (int r = 0; r <= R; r++) {
        g_off[r] = off;
        g_cur[r] = off;
        off += ((g_cnt[r] + TM - 1) / TM) * TM;
    }
    g_off[R + 1] = off;
    g_ntiles = off / TM;
}

// launch #4: two-phase scatter + self-loops + padding (disjoint index ranges)
__global__ void k_scatter(const void* __restrict__ ei,
                          const void* __restrict__ et,
                          int E, int N, int R) {
    __shared__ int cnt[RMAX + 1];
    __shared__ int base[RMAX + 1];
    int i = blockIdx.x * blockDim.x + threadIdx.x;
    int is64 = g_is64;

    if (threadIdx.x <= R) cnt[threadIdx.x] = 0;
    __syncthreads();

    int r = -1, s = 0, d = 0, slot = 0;
    if (i < E) {
        if (is64) {
            r = (int)((const long long*)et)[i];
            s = (int)((const long long*)ei)[i];
            d = (int)((const long long*)ei)[E + i];
        } else {
            r = ((const int*)et)[i];
            s = ((const int*)ei)[i];
            d = ((const int*)ei)[E + i];
        }
        if (r < 0) r = 0;
        if (r >= R) r = R - 1;
        if (s < 0 || s >= N) s = 0;
        if (d < 0 || d >= N) d = 0;
        slot = atomicAdd(&cnt[r], 1);
    }
    __syncthreads();
    if (threadIdx.x <= R && cnt[threadIdx.x] > 0)
        base[threadIdx.x] = atomicAdd(&g_cur[threadIdx.x], cnt[threadIdx.x]);
    __syncthreads();

    if (r >= 0) {
        int p = base[r] + slot;
        g_srcbuf[p] = s;
        g_dstbuf[p] = d;
    } else if (i >= E && i < E + N) {
        int n = i - E;
        int p = g_off[R] + n;
        g_srcbuf[p] = n;
        g_dstbuf[p] = n;
    } else if (i >= E + N) {
        int j = i - (E + N);
        int rr = j / TM;
        int jj = j % TM;
        if (rr <= R) {
            int idx = g_off[rr] + g_cnt[rr] + jj;
            if (idx < g_off[rr + 1]) {
                g_srcbuf[idx] = -1;
                g_dstbuf[idx] = 0;
            }
        }
    }
}

// launch #5: x, W -> fp16 (vectorized); init out = bias
__global__ void k_prep(const float* __restrict__ x,
                       const float* __restrict__ W_rel,
                       const float* __restrict__ W_self,
                       const float* __restrict__ bias,
                       float* __restrict__ out,
                       int total4, int wtotal4, int R) {
    int i = blockIdx.x * blockDim.x + threadIdx.x;
    if (i < total4) {
        float4 v = ((const float4*)x)[i];
        __half2* dst = (__half2*)&g_xh[i * 4];
        dst[0] = __floats2half2_rn(v.x, v.y);
        dst[1] = __floats2half2_rn(v.z, v.w);
        ((float4*)out)[i] = ((const float4*)bias)[i & (D / 4 - 1)];
    }
    if (i < wtotal4) {
        int wr = R * D * D / 4;
        float4 v = (i < wr) ? ((const float4*)W_rel)[i]
                            : ((const float4*)W_self)[i - wr];
        __half2* dst = (__half2*)&g_wh[i * 4];
        dst[0] = __floats2half2_rn(v.x, v.y);
        dst[1] = __floats2half2_rn(v.z, v.w);
    }
}

// launch #7 (vectorized)
__global__ void k_relu(float* __restrict__ out, int total4) {
    int i = blockIdx.x * blockDim.x + threadIdx.x;
    if (i < total4) {
        float4 v = ((const float4*)out)[i];
        v.x = fmaxf(v.x, 0.0f);
        v.y = fmaxf(v.y, 0.0f);
        v.z = fmaxf(v.z, 0.0f);
        v.w = fmaxf(v.w, 0.0f);
        ((float4*)out)[i] = v;
    }
}

// ---------------------------------------------------------------------------
__device__ __forceinline__ uint32_t smem_u32(const void* p) {
    return (uint32_t)__cvta_generic_to_shared(p);
}

__device__ __forceinline__ void cpa16(uint32_t dst, const void* src, int sz) {
    asm volatile("cp.async.cg.shared.global [%0], [%1], 16, %2;"
                 :: "r"(dst), "l"(src), "r"(sz) : "memory");
}

__device__ __forceinline__ void ldsm_x4(uint32_t* r, uint32_t addr) {
    asm volatile("ldmatrix.sync.aligned.m8n8.x4.shared.b16 {%0,%1,%2,%3}, [%4];"
                 : "=r"(r[0]), "=r"(r[1]), "=r"(r[2]), "=r"(r[3]) : "r"(addr));
}

__device__ __forceinline__ void ldsm_x4_t(uint32_t* r, uint32_t addr) {
    asm volatile("ldmatrix.sync.aligned.m8n8.x4.trans.shared.b16 {%0,%1,%2,%3}, [%4];"
                 : "=r"(r[0]), "=r"(r[1]), "=r"(r[2]), "=r"(r[3]) : "r"(addr));
}

__device__ __forceinline__ void mma_f16(float* c, const uint32_t* a, const uint32_t* b) {
    asm volatile(
        "mma.sync.aligned.m16n8k16.row.col.f32.f16.f16.f32 "
        "{%0,%1,%2,%3}, {%4,%5,%6,%7}, {%8,%9}, {%0,%1,%2,%3};"
        : "+f"(c[0]), "+f"(c[1]), "+f"(c[2]), "+f"(c[3])
        : "r"(a[0]), "r"(a[1]), "r"(a[2]), "r"(a[3]), "r"(b[0]), "r"(b[1]));
}

// smem: A resident 128 rows x 512B (XOR-swizzled 16B chunks within row) = 65536
//       B ring: 2 stages x (64 rows x 272B) = 34816; idx arrays 1024
#define ABYTES (TM * 512)
#define BSTRB 272
#define BSTAGE (KC * BSTRB)              // 17408
#define OFF_AF 0
#define OFF_BST ABYTES                   // 65536
#define OFF_SRC (OFF_BST + 2 * BSTAGE)   // 100352
#define OFF_DST (OFF_SRC + 512)
#define SMEM_TOTAL (OFF_DST + 512)       // 101376  (2 CTA/SM)

// grid: tiles_max; block 256 = 8 warps; warp grid 4(M) x 2(N), tile 32x64;
// CTA covers full TN=256 by looping y in {0,1} with resident A.
__global__ __launch_bounds__(256, 2) void k_gemm(float* __restrict__ out, int R) {
    extern __shared__ __align__(16) char sh[];
    int t = blockIdx.x;
    if (t >= g_ntiles) return;
    int row0 = t * TM;

    int rel = 0;
    while (g_off[rel + 1] <= row0) rel++;
    int relk = rel * D;                       // W row base in [r*D + k][n]

    int tid = threadIdx.x;
    int warp = tid >> 5;
    int lane = tid & 31;
    int wm = (warp & 3) * 32;      // M offset (4 warps along M)
    int wn = (warp >> 2) * 64;     // N offset within 128-col half (2 warps along N)

    int* s_src = (int*)(sh + OFF_SRC);
    int* s_dst = (int*)(sh + OFF_DST);
    if (tid < TM) {
        s_src[tid] = g_srcbuf[row0 + tid];
        s_dst[tid] = g_dstbuf[row0 + tid];
    }
    __syncthreads();

    uint32_t shb = smem_u32(sh);

    // ---- A fill (once): 128 rows x 512B, 16B ops, XOR swizzle within row ----
    #pragma unroll 4
    for (int ii = 0; ii < 16; ii++) {
        int j = tid + ii * 256;               // 0..4095
        int rr = j >> 5;                      // row
        int cb = (j & 31) << 4;               // col byte 0..496
        int sw = cb ^ ((rr & 7) << 4);
        int sr = s_src[rr];
        int sz = (sr < 0) ? 0 : 16;
        cpa16(shb + OFF_AF + rr * 512 + sw,
              &g_xh[(size_t)max(sr, 0) * D + (j & 31) * 8], sz);
    }
    asm volatile("cp.async.commit_group;" ::: "memory");

    // ---- B fill for step s (y = s>>2, chunk = s&3): 1024 x 16B ops ----
    #define FILLB(stg, s_) do {                                                \
        uint32_t sb = shb + OFF_BST + (stg) * BSTAGE;                          \
        int y_ = (s_) >> 2, c_ = (s_) & 3;                                     \
        int kb = relk + c_ * KC;                                               \
        _Pragma("unroll")                                                      \
        for (int ii = 0; ii < 4; ii++) {                                       \
            int j = tid + ii * 256;                                            \
            int br = j >> 4, bs = j & 15;                                      \
            size_t bi = (size_t)(kb + br) * D + y_ * 128 + bs * 8;             \
            cpa16(sb + br * BSTRB + bs * 16, &g_wh[bi], 16);                   \
        }                                                                      \
        asm volatile("cp.async.commit_group;" ::: "memory");                   \
    } while (0)

    float acc[2][8][4];
    #pragma unroll
    for (int mi = 0; mi < 2; mi++)
        #pragma unroll
        for (int g = 0; g < 8; g++)
            #pragma unroll
            for (int j = 0; j < 4; j++) acc[mi][g][j] = 0.0f;

    // ldmatrix lane addressing
    int a_row = (lane & 15);                  // + wm + mi*16
    int a_cbyte = (lane >> 4) << 4;           // 0 / 16 bytes
    int a_swx = (lane & 7) << 4;              // row-dependent XOR term
    int b_mat = lane >> 3;
    int b_rowoff = (lane & 7) + (b_mat & 1) * 8;
    int b_cbyte = ((b_mat >> 1) << 3) * 2;    // 0 / 16 bytes within 16-col pair

    FILLB(0, 0);

    #pragma unroll 1
    for (int s = 0; s < 8; s++) {
        asm volatile("cp.async.wait_group 0;" ::: "memory");
        __syncthreads();
        // prefetch next step's B into stage (s+1)&1: its last reader (step s-1)
        // finished before this barrier — safe with 2 stages.
        if (s < 7) FILLB((s + 1) & 1, s + 1);

        int c = s & 3;
        uint32_t sb = shb + OFF_BST + (s & 1) * BSTAGE;
        #pragma unroll
        for (int ks = 0; ks < 4; ks++) {       // four k16 steps per chunk
            int cb = c * 128 + ks * 32 + a_cbyte;
            uint32_t a[2][4];
            #pragma unroll
            for (int mi = 0; mi < 2; mi++) {
                int arow = wm + mi * 16 + a_row;
                ldsm_x4(a[mi], shb + OFF_AF + arow * 512 + (cb ^ a_swx));
            }
            #pragma unroll
            for (int p = 0; p < 4; p++) {      // 16-col pairs within 64
                uint32_t b[4];
                ldsm_x4_t(b, sb + (ks * 16 + b_rowoff) * BSTRB
                             + wn * 2 + p * 32 + b_cbyte);
                #pragma unroll
                for (int mi = 0; mi < 2; mi++) {
                    mma_f16(acc[mi][2 * p],     a[mi], &b[0]);
                    mma_f16(acc[mi][2 * p + 1], a[mi], &b[2]);
                }
            }
        }

        // ---- per-y epilogue after the 4th chunk; overlaps next y's B fill ----
        if (c == 3) {
            int y = s >> 2;
            #pragma unroll
            for (int mi = 0; mi < 2; mi++) {
                int lr0 = wm + mi * 16 + (lane >> 2);
                int lr1 = lr0 + 8;
                int s0 = s_src[lr0], s1 = s_src[lr1];
                long long d0 = (long long)s_dst[lr0] * D;
                long long d1 = (long long)s_dst[lr1] * D;
                int colb = y * 128 + wn + ((lane & 3) << 1);
                #pragma unroll
                for (int g = 0; g < 8; g++) {
                    int col = colb + g * 8;
                    if (s0 >= 0) {
                        float* p = out + d0 + col;
                        asm volatile("red.global.add.v2.f32 [%0], {%1, %2};"
                                     :: "l"(p), "f"(acc[mi][g][0]), "f"(acc[mi][g][1])
                                     : "memory");
                    }
                    if (s1 >= 0) {
                        float* p = out + d1 + col;
                        asm volatile("red.global.add.v2.f32 [%0], {%1, %2};"
                                     :: "l"(p), "f"(acc[mi][g][2]), "f"(acc[mi][g][3])
                                     : "memory");
                    }
                }
            }
            #pragma unroll
            for (int mi = 0; mi < 2; mi++)
                #pragma unroll
                for (int g = 0; g < 8; g++)
                    #pragma unroll
                    for (int j = 0; j < 4; j++) acc[mi][g][j] = 0.0f;
        }
    }
}

// ---------------------------------------------------------------------------
extern "C" void kernel_launch(void* const* d_in, const int* in_sizes, int n_in,
                              void* d_out, int out_size) {
    // Bind inputs by element count (all six pairwise distinct):
    //   bias(256) < W_self(65,536) < edge_type(800k) < W_rel(1,048,576)
    //   < edge_index(1.6M) < x(12.8M)
    int order[16];
    for (int i = 0; i < n_in; i++) order[i] = i;
    for (int a = 0; a < n_in; a++)
        for (int b = a + 1; b < n_in; b++)
            if (in_sizes[order[b]] < in_sizes[order[a]]) {
                int t = order[a]; order[a] = order[b]; order[b] = t;
            }
    const float* bias   = (const float*)d_in[order[0]];
    const float* W_self = (const float*)d_in[order[1]];
    const void*  et     = d_in[order[2]];
    const float* W_rel  = (const float*)d_in[order[3]];
    const void*  ei     = d_in[order[4]];
    const float* x      = (const float*)d_in[order[5]];

    int E = in_sizes[order[2]];
    int N = in_sizes[order[5]] / D;
    int R = in_sizes[order[3]] / (D * D);
    if (R < 1) R = 1;
    if (R > RMAX - 1) R = RMAX - 1;
    if (N > MAXN) N = MAXN;

    float* out = (float*)d_out;
    int total = N * D;
    int wtotal = (R + 1) * D * D;

    k_detect<<<1, 256>>>((const int2*)ei, 256, R);
    k_hist<<<(E + 255) / 256, 256>>>(et, E, R);
    k_scan<<<1, 1>>>(R, N);
    int scat_total = E + N + (R + 1) * TM;
    k_scatter<<<(scat_total + 255) / 256, 256>>>(ei, et, E, N, R);
    k_prep<<<(total / 4 + 255) / 256, 256>>>(x, W_rel, W_self, bias, out,
                                             total / 4, wtotal / 4, R);

    cudaFuncSetAttribute(k_gemm, cudaFuncAttributeMaxDynamicSharedMemorySize, SMEM_TOTAL);
    int tiles_max = (E + TM - 1) / TM + R + (N + TM - 1) / TM + 1;
    k_gemm<<<tiles_max, 256, SMEM_TOTAL>>>(out, R);

    k_relu<<<(total / 4 + 255) / 256, 256>>>(out, total / 4);
}